// round 1
// baseline (speedup 1.0000x reference)
#include <cuda_runtime.h>
#include <math.h>

#define SCALE 16
#define R_MAX 4
#define NOFF 81   // (2*R_MAX+1)^2
#define HL 32
#define WL 32
#define HH 512
#define WH 512
#define C_FEAT 128
#define C_GUIDE 3

// Scratch: precomputed low-res guide (3x32x32) and channel-minor transposed features (32*32 x 128).
__device__ float g_guide_lr[C_GUIDE * HL * WL];
__device__ float g_feat_t[HL * WL * C_FEAT];

// ---------------------------------------------------------------------------
// Prep kernel: (a) transpose feat to spatial-major/channel-minor for coalesced
// smem fills; (b) bilinear-downsample guide 512->32 reproducing the reference's
// separable row-then-column math.
// ---------------------------------------------------------------------------
__global__ void jbu_prep_kernel(const float* __restrict__ feat,
                                const float* __restrict__ guide) {
    int idx = blockIdx.x * blockDim.x + threadIdx.x;

    // feat transpose: 32*32*128 = 131072 elements
    if (idx < HL * WL * C_FEAT) {
        int c = idx & (C_FEAT - 1);
        int s = idx >> 7;                 // spatial index ui*32+vi
        g_feat_t[idx] = feat[c * (HL * WL) + s];
    }

    // guide downsample: 3*32*32 = 3072 outputs
    if (idx < C_GUIDE * HL * WL) {
        int c = idx >> 10;                // /1024
        int rem = idx & 1023;
        int i = rem >> 5;
        int j = rem & 31;

        float srcy = fmaxf((i + 0.5f) * ((float)HH / HL) - 0.5f, 0.0f);
        int r0 = (int)floorf(srcy);
        float tr = srcy - (float)r0;
        int r0c = min(max(r0, 0), HH - 1);
        int r1c = min(max(r0 + 1, 0), HH - 1);

        float srcx = fmaxf((j + 0.5f) * ((float)WH / WL) - 0.5f, 0.0f);
        int c0 = (int)floorf(srcx);
        float tc = srcx - (float)c0;
        int c0c = min(max(c0, 0), WH - 1);
        int c1c = min(max(c0 + 1, 0), WH - 1);

        const float* g = guide + c * (HH * WH);
        // rows first (match reference ordering), then columns
        float v0 = g[r0c * WH + c0c] * (1.0f - tr) + g[r1c * WH + c0c] * tr;
        float v1 = g[r0c * WH + c1c] * (1.0f - tr) + g[r1c * WH + c1c] * tr;
        g_guide_lr[idx] = v0 * (1.0f - tc) + v1 * tc;
    }
}

// ---------------------------------------------------------------------------
// Main JBU kernel. One block per LR cell (16x16 HR tile). 256 threads = pixels.
// Per-block: params are uniform -> compact the active offset list (mask is
// block-uniform), stage F[off][128] in smem, then each thread accumulates all
// 128 channels in registers via packed f32x2 FMAs.
// ---------------------------------------------------------------------------
__global__ __launch_bounds__(256, 1)
void jbu_main_kernel(const float* __restrict__ guide,
                     const float* __restrict__ sx_raw,
                     const float* __restrict__ sy_raw,
                     const float* __restrict__ th_raw,
                     const float* __restrict__ sr_raw,
                     float* __restrict__ out) {
    __shared__ __align__(16) float Fsh[NOFF * C_FEAT];   // 41472 B
    __shared__ float s_fdx[NOFF];
    __shared__ float s_fdy[NOFF];
    __shared__ int   s_si[NOFF];
    __shared__ float s_par[5];  // cos, sin, inv2sx2, inv2sy2, inv2sr2
    __shared__ int   s_nact;

    const int uc = blockIdx.y;
    const int vc = blockIdx.x;
    const int tid = threadIdx.x;
    const int ty = tid >> 4;
    const int tx = tid & 15;

    if (tid == 0) {
        int cell = uc * WL + vc;
        float sx = fmaxf(expf(sx_raw[cell]), 1e-6f);
        float sy = fmaxf(expf(sy_raw[cell]), 1e-6f);
        float th = 3.14159265358979323846f * tanhf(th_raw[cell]);
        float sr = fmaxf(expf(sr_raw[cell]), 1e-6f);
        float rr = fminf(fmaxf(2.0f * fmaxf(sx, sy), 1.0f), (float)R_MAX);
        float Rsq = rr * rr;
        s_par[0] = cosf(th);
        s_par[1] = sinf(th);
        s_par[2] = 1.0f / (2.0f * sx * sx + 1e-8f);
        s_par[3] = 1.0f / (2.0f * sy * sy + 1e-8f);
        s_par[4] = 1.0f / (2.0f * sr * sr + 1e-8f);

        int n = 0;
        // reference scan order: dy outer (slow), dx inner (fast)
        for (int dy = -R_MAX; dy <= R_MAX; dy++) {
            for (int dx = -R_MAX; dx <= R_MAX; dx++) {
                if ((float)(dy * dy + dx * dx) <= Rsq) {
                    int ui = min(max(uc + dy, 0), HL - 1);
                    int vi = min(max(vc + dx, 0), WL - 1);
                    s_fdy[n] = (float)(uc - ui);
                    s_fdx[n] = (float)(vc - vi);
                    s_si[n]  = ui * WL + vi;
                    n++;
                }
            }
        }
        s_nact = n;
    }
    __syncthreads();

    const int nact = s_nact;

    // Stage F: coalesced 512B per active offset
    for (int i = tid; i < nact * C_FEAT; i += 256) {
        Fsh[i] = g_feat_t[s_si[i >> 7] * C_FEAT + (i & (C_FEAT - 1))];
    }
    __syncthreads();

    const int y = uc * SCALE + ty;
    const int x = vc * SCALE + tx;
    const float* gpix = guide + y * WH + x;
    const float g0 = gpix[0];
    const float g1 = gpix[HH * WH];
    const float g2 = gpix[2 * HH * WH];

    const float px = ((float)tx - 7.5f) * (1.0f / SCALE);
    const float py = ((float)ty - 7.5f) * (1.0f / SCALE);
    const float ct  = s_par[0];
    const float st  = s_par[1];
    const float isx = s_par[2];
    const float isy = s_par[3];
    const float isr = s_par[4];

    unsigned long long acc[64];
#pragma unroll
    for (int j = 0; j < 64; j++) acc[j] = 0ULL;
    float den = 0.0f;

    unsigned smem_base;
    asm("{ .reg .u64 t; cvta.to.shared.u64 t, %1; cvt.u32.u64 %0, t; }"
        : "=r"(smem_base) : "l"(Fsh));

    for (int k = 0; k < nact; k++) {
        float cdx = px + s_fdx[k];
        float cdy = py + s_fdy[k];
        float a = cdx * ct + cdy * st;
        float b = cdy * ct - cdx * st;
        int si = s_si[k];
        float d0 = g0 - g_guide_lr[si];
        float d1 = g1 - g_guide_lr[HL * WL + si];
        float d2 = g2 - g_guide_lr[2 * HL * WL + si];
        float gd2 = d0 * d0 + d1 * d1 + d2 * d2;
        float lw = -(a * a * isx + b * b * isy + gd2 * isr);
        float w = __expf(lw);
        den += w;

        unsigned long long w2;
        unsigned wu = __float_as_uint(w);
        asm("mov.b64 %0, {%1, %1};" : "=l"(w2) : "r"(wu));

        unsigned addr = smem_base + (unsigned)(k * (C_FEAT * 4));
#pragma unroll
        for (int j = 0; j < 32; j++) {
            unsigned long long f01, f23;
            asm("ld.shared.v2.b64 {%0, %1}, [%2];"
                : "=l"(f01), "=l"(f23) : "r"(addr + j * 16));
            asm("fma.rn.f32x2 %0, %1, %2, %0;" : "+l"(acc[2 * j])     : "l"(f01), "l"(w2));
            asm("fma.rn.f32x2 %0, %1, %2, %0;" : "+l"(acc[2 * j + 1]) : "l"(f23), "l"(w2));
        }
    }

    const float inv = 1.0f / fmaxf(den, 1e-8f);
    float* op = out + y * WH + x;
#pragma unroll
    for (int j = 0; j < 64; j++) {
        unsigned lo_u, hi_u;
        asm("mov.b64 {%0, %1}, %2;" : "=r"(lo_u), "=r"(hi_u) : "l"(acc[j]));
        op[(2 * j) * (HH * WH)]     = __uint_as_float(lo_u) * inv;
        op[(2 * j + 1) * (HH * WH)] = __uint_as_float(hi_u) * inv;
    }
}

extern "C" void kernel_launch(void* const* d_in, const int* in_sizes, int n_in,
                              void* d_out, int out_size) {
    const float* feat  = (const float*)d_in[0];
    const float* guide = (const float*)d_in[1];
    const float* sx    = (const float*)d_in[2];
    const float* sy    = (const float*)d_in[3];
    const float* th    = (const float*)d_in[4];
    const float* sr    = (const float*)d_in[5];
    float* out = (float*)d_out;

    jbu_prep_kernel<<<512, 256>>>(feat, guide);
    dim3 grid(WL, HL);
    jbu_main_kernel<<<grid, 256>>>(guide, sx, sy, th, sr, out);
}

// round 2
// speedup vs baseline: 1.0659x; 1.0659x over previous
#include <cuda_runtime.h>
#include <math.h>

#define SCALE 16
#define R_MAX 4
#define NOFF 81   // (2*R_MAX+1)^2
#define HL 32
#define WL 32
#define HH 512
#define WH 512
#define C_FEAT 128
#define C_GUIDE 3

// Scratch: precomputed low-res guide (3x32x32) and channel-minor transposed features.
__device__ float g_guide_lr[C_GUIDE * HL * WL];
__device__ float g_feat_t[HL * WL * C_FEAT];

// ---------------------------------------------------------------------------
// Prep kernel: transpose feat to channel-minor; bilinear-downsample guide
// (separable, rows then columns, matching the reference).
// ---------------------------------------------------------------------------
__global__ void jbu_prep_kernel(const float* __restrict__ feat,
                                const float* __restrict__ guide) {
    int idx = blockIdx.x * blockDim.x + threadIdx.x;

    if (idx < HL * WL * C_FEAT) {
        int c = idx & (C_FEAT - 1);
        int s = idx >> 7;
        g_feat_t[idx] = feat[c * (HL * WL) + s];
    }

    if (idx < C_GUIDE * HL * WL) {
        int c = idx >> 10;
        int rem = idx & 1023;
        int i = rem >> 5;
        int j = rem & 31;

        float srcy = fmaxf((i + 0.5f) * ((float)HH / HL) - 0.5f, 0.0f);
        int r0 = (int)floorf(srcy);
        float tr = srcy - (float)r0;
        int r0c = min(max(r0, 0), HH - 1);
        int r1c = min(max(r0 + 1, 0), HH - 1);

        float srcx = fmaxf((j + 0.5f) * ((float)WH / WL) - 0.5f, 0.0f);
        int c0 = (int)floorf(srcx);
        float tc = srcx - (float)c0;
        int c0c = min(max(c0, 0), WH - 1);
        int c1c = min(max(c0 + 1, 0), WH - 1);

        const float* g = guide + c * (HH * WH);
        float v0 = g[r0c * WH + c0c] * (1.0f - tr) + g[r1c * WH + c0c] * tr;
        float v1 = g[r0c * WH + c1c] * (1.0f - tr) + g[r1c * WH + c1c] * tr;
        g_guide_lr[idx] = v0 * (1.0f - tc) + v1 * tc;
    }
}

// ---------------------------------------------------------------------------
// Main JBU kernel. One block per LR cell. 512 threads: thread = (pixel,
// channel-half). Per-offset weight params are fully hoisted:
//   a = pa + A_k,  b = pb + B_k
//   lw = (g0*c0k + g1*c1k + g2*c2k) + negE - D_k - a^2*isx - b^2*isy
// where A,B,D,c* are per-offset constants in smem and pa,pb,negE per-pixel regs.
// ---------------------------------------------------------------------------
__global__ __launch_bounds__(512, 1)
void jbu_main_kernel(const float* __restrict__ guide,
                     const float* __restrict__ sx_raw,
                     const float* __restrict__ sy_raw,
                     const float* __restrict__ th_raw,
                     const float* __restrict__ sr_raw,
                     float* __restrict__ out) {
    __shared__ __align__(16) float Fsh[NOFF * C_FEAT];   // 41472 B
    __shared__ __align__(16) float4 s_p0[NOFF];          // A, B, D, c0
    __shared__ __align__(8)  float2 s_p1[NOFF];          // c1, c2
    __shared__ float s_dxf[NOFF];
    __shared__ float s_dyf[NOFF];
    __shared__ int   s_si[NOFF];
    __shared__ float s_scal[5];  // ct, st, isx, isy, isr
    __shared__ int   s_nact;

    const int uc = blockIdx.y;
    const int vc = blockIdx.x;
    const int tid = threadIdx.x;
    const int pix = tid & 255;
    const int ty  = pix >> 4;
    const int tx  = pix & 15;
    const int choff = (tid >> 8) << 6;   // 0 or 64

    if (tid == 0) {
        int cell = uc * WL + vc;
        float sx = fmaxf(expf(sx_raw[cell]), 1e-6f);
        float sy = fmaxf(expf(sy_raw[cell]), 1e-6f);
        float th = 3.14159265358979323846f * tanhf(th_raw[cell]);
        float sr = fmaxf(expf(sr_raw[cell]), 1e-6f);
        float rr = fminf(fmaxf(2.0f * fmaxf(sx, sy), 1.0f), (float)R_MAX);
        float Rsq = rr * rr;
        s_scal[0] = cosf(th);
        s_scal[1] = sinf(th);
        s_scal[2] = 1.0f / (2.0f * sx * sx + 1e-8f);
        s_scal[3] = 1.0f / (2.0f * sy * sy + 1e-8f);
        s_scal[4] = 1.0f / (2.0f * sr * sr + 1e-8f);

        int n = 0;
        for (int dy = -R_MAX; dy <= R_MAX; dy++) {
            for (int dx = -R_MAX; dx <= R_MAX; dx++) {
                if ((float)(dy * dy + dx * dx) <= Rsq) {
                    int ui = min(max(uc + dy, 0), HL - 1);
                    int vi = min(max(vc + dx, 0), WL - 1);
                    s_dyf[n] = (float)(uc - ui);
                    s_dxf[n] = (float)(vc - vi);
                    s_si[n]  = ui * WL + vi;
                    n++;
                }
            }
        }
        s_nact = n;
    }
    __syncthreads();

    const int nact = s_nact;
    const float ct  = s_scal[0];
    const float st  = s_scal[1];
    const float isx = s_scal[2];
    const float isy = s_scal[3];
    const float isr = s_scal[4];

    // Per-offset derived params (parallel over offsets)
    if (tid < nact) {
        int si = s_si[tid];
        float fdx = s_dxf[tid];
        float fdy = s_dyf[tid];
        float gl0 = g_guide_lr[si];
        float gl1 = g_guide_lr[HL * WL + si];
        float gl2 = g_guide_lr[2 * HL * WL + si];
        float A = fdx * ct + fdy * st;
        float B = fdy * ct - fdx * st;
        float D = (gl0 * gl0 + gl1 * gl1 + gl2 * gl2) * isr;
        s_p0[tid] = make_float4(A, B, D, 2.0f * gl0 * isr);
        s_p1[tid] = make_float2(2.0f * gl1 * isr, 2.0f * gl2 * isr);
    }

    // Stage F: coalesced 512B per active offset, all 512 threads
    for (int i = tid; i < nact * C_FEAT; i += 512) {
        Fsh[i] = g_feat_t[s_si[i >> 7] * C_FEAT + (i & (C_FEAT - 1))];
    }
    __syncthreads();

    const int y = uc * SCALE + ty;
    const int x = vc * SCALE + tx;
    const float* gpix = guide + y * WH + x;
    const float g0 = gpix[0];
    const float g1 = gpix[HH * WH];
    const float g2 = gpix[2 * HH * WH];

    const float px = ((float)tx - 7.5f) * (1.0f / SCALE);
    const float py = ((float)ty - 7.5f) * (1.0f / SCALE);
    const float pa = px * ct + py * st;
    const float pb = py * ct - px * st;
    const float negE = -(g0 * g0 + g1 * g1 + g2 * g2) * isr;
    const float nisx = -isx;
    const float nisy = -isy;

    unsigned long long acc[32];
#pragma unroll
    for (int j = 0; j < 32; j++) acc[j] = 0ULL;
    float den = 0.0f;

    unsigned smem_base;
    asm("{ .reg .u64 t; cvta.to.shared.u64 t, %1; cvt.u32.u64 %0, t; }"
        : "=r"(smem_base) : "l"(Fsh));
    const unsigned ch_byte = (unsigned)(choff * 4);

    for (int k = 0; k < nact; k++) {
        float4 p0 = s_p0[k];
        float2 p1 = s_p1[k];
        float a = pa + p0.x;
        float b = pb + p0.y;
        float t = negE - p0.z;
        t = fmaf(g0, p0.w, t);
        t = fmaf(g1, p1.x, t);
        t = fmaf(g2, p1.y, t);
        t = fmaf(a * a, nisx, t);
        t = fmaf(b * b, nisy, t);
        float w = __expf(t);
        den += w;

        unsigned long long w2;
        unsigned wu = __float_as_uint(w);
        asm("mov.b64 %0, {%1, %1};" : "=l"(w2) : "r"(wu));

        unsigned addr = smem_base + (unsigned)(k * (C_FEAT * 4)) + ch_byte;
#pragma unroll
        for (int j = 0; j < 16; j++) {
            unsigned long long f01, f23;
            asm("ld.shared.v2.b64 {%0, %1}, [%2];"
                : "=l"(f01), "=l"(f23) : "r"(addr + j * 16));
            asm("fma.rn.f32x2 %0, %1, %2, %0;" : "+l"(acc[2 * j])     : "l"(f01), "l"(w2));
            asm("fma.rn.f32x2 %0, %1, %2, %0;" : "+l"(acc[2 * j + 1]) : "l"(f23), "l"(w2));
        }
    }

    const float inv = 1.0f / fmaxf(den, 1e-8f);
    float* op = out + (size_t)choff * (HH * WH) + y * WH + x;
#pragma unroll
    for (int j = 0; j < 32; j++) {
        unsigned lo_u, hi_u;
        asm("mov.b64 {%0, %1}, %2;" : "=r"(lo_u), "=r"(hi_u) : "l"(acc[j]));
        op[(2 * j) * (HH * WH)]     = __uint_as_float(lo_u) * inv;
        op[(2 * j + 1) * (HH * WH)] = __uint_as_float(hi_u) * inv;
    }
}

extern "C" void kernel_launch(void* const* d_in, const int* in_sizes, int n_in,
                              void* d_out, int out_size) {
    const float* feat  = (const float*)d_in[0];
    const float* guide = (const float*)d_in[1];
    const float* sx    = (const float*)d_in[2];
    const float* sy    = (const float*)d_in[3];
    const float* th    = (const float*)d_in[4];
    const float* sr    = (const float*)d_in[5];
    float* out = (float*)d_out;

    jbu_prep_kernel<<<512, 256>>>(feat, guide);
    dim3 grid(WL, HL);
    jbu_main_kernel<<<grid, 512>>>(guide, sx, sy, th, sr, out);
}

// round 4
// speedup vs baseline: 1.2870x; 1.2074x over previous
#include <cuda_runtime.h>
#include <math.h>
#include <stdint.h>

#define SCALE 16
#define R_MAX 4
#define HL 32
#define WL 32
#define HH 512
#define WH 512
#define C_FEAT 128
#define HW (HH * WH)

// prep scratch
__device__ float g_guide_lr[3 * HL * WL];
__device__ float g_feat_t[HL * WL * C_FEAT];   // [spatial][channel]

// ---------------- dynamic smem layout (bytes) ----------------
// K padded to <=56; hi/lo interleaved -> row stride 114 floats (57 float2)
#define KSTRIDE_F  114
#define OFF_SCAL   0            // 8 floats
#define OFF_NACT   32           // int
#define OFF_SI     64           // int[64]
#define OFF_DXF    320          // float[64]
#define OFF_DYF    576          // float[64]
#define OFF_P0     832          // float4[64]
#define OFF_P1     1856         // float2[64]
#define OFF_DEN    2368         // float[256]
#define OFF_W      3392         // 256 * 114 floats = 116736 B
#define OFF_F      (OFF_W + 256 * KSTRIDE_F * 4)     // 128 * 114 floats = 58368 B
#define SMEM_BYTES (OFF_F + 128 * KSTRIDE_F * 4)     // 178496 B

static __device__ __forceinline__ uint32_t f2tf32(float f) {
    uint32_t r;
    asm("cvt.rna.tf32.f32 %0, %1;" : "=r"(r) : "f"(f));
    return r;
}

#define MMA_TF32(d, a0, a1, a2, a3, b0, b1) \
    asm volatile("mma.sync.aligned.m16n8k8.row.col.f32.tf32.tf32.f32 " \
        "{%0,%1,%2,%3}, {%4,%5,%6,%7}, {%8,%9}, {%0,%1,%2,%3};" \
        : "+f"((d)[0]), "+f"((d)[1]), "+f"((d)[2]), "+f"((d)[3]) \
        : "r"(a0), "r"(a1), "r"(a2), "r"(a3), "r"(b0), "r"(b1))

// ---------------------------------------------------------------------------
// Prep: transpose feat to channel-minor; bilinear-downsample guide (separable,
// rows then columns, matching the reference).
// ---------------------------------------------------------------------------
__global__ void jbu_prep_kernel(const float* __restrict__ feat,
                                const float* __restrict__ guide) {
    int idx = blockIdx.x * blockDim.x + threadIdx.x;

    if (idx < HL * WL * C_FEAT) {
        int c = idx & (C_FEAT - 1);
        int s = idx >> 7;
        g_feat_t[idx] = feat[c * (HL * WL) + s];
    }
    if (idx < 3 * HL * WL) {
        int c = idx >> 10;
        int rem = idx & 1023;
        int i = rem >> 5;
        int j = rem & 31;

        float srcy = fmaxf((i + 0.5f) * ((float)HH / HL) - 0.5f, 0.0f);
        int r0 = (int)floorf(srcy);
        float tr = srcy - (float)r0;
        int r0c = min(max(r0, 0), HH - 1);
        int r1c = min(max(r0 + 1, 0), HH - 1);

        float srcx = fmaxf((j + 0.5f) * ((float)WH / WL) - 0.5f, 0.0f);
        int c0 = (int)floorf(srcx);
        float tc = srcx - (float)c0;
        int c0c = min(max(c0, 0), WH - 1);
        int c1c = min(max(c0 + 1, 0), WH - 1);

        const float* g = guide + c * HW;
        float v0 = g[r0c * WH + c0c] * (1.0f - tr) + g[r1c * WH + c0c] * tr;
        float v1 = g[r0c * WH + c1c] * (1.0f - tr) + g[r1c * WH + c1c] * tr;
        g_guide_lr[idx] = v0 * (1.0f - tc) + v1 * tc;
    }
}

// ---------------------------------------------------------------------------
// Main: one block per LR cell. num = W[256xK] * F[Kx128] via mma.sync tf32
// with 2-plane split (hh + lh + hl). den exact fp32 during W build.
// ---------------------------------------------------------------------------
__global__ __launch_bounds__(512, 1)
void jbu_main_kernel(const float* __restrict__ guide,
                     const float* __restrict__ sx_raw,
                     const float* __restrict__ sy_raw,
                     const float* __restrict__ th_raw,
                     const float* __restrict__ sr_raw,
                     float* __restrict__ out) {
    extern __shared__ __align__(16) char smem[];

    float*  s_scal = (float*)(smem + OFF_SCAL);
    int*    s_nactp = (int*)(smem + OFF_NACT);
    int*    s_si   = (int*)(smem + OFF_SI);
    float*  s_dxf  = (float*)(smem + OFF_DXF);
    float*  s_dyf  = (float*)(smem + OFF_DYF);
    float4* s_p0   = (float4*)(smem + OFF_P0);
    float2* s_p1   = (float2*)(smem + OFF_P1);
    float*  s_den  = (float*)(smem + OFF_DEN);
    float*  Wf     = (float*)(smem + OFF_W);
    float*  Ff     = (float*)(smem + OFF_F);

    const int uc = blockIdx.y;
    const int vc = blockIdx.x;
    const int tid = threadIdx.x;
    const int wid = tid >> 5;
    const int lane = tid & 31;

    // ---- phase 0: per-cell params + offset compaction ----
    if (tid == 0) {
        int cell = uc * WL + vc;
        float sx = fmaxf(expf(sx_raw[cell]), 1e-6f);
        float sy = fmaxf(expf(sy_raw[cell]), 1e-6f);
        float th = 3.14159265358979323846f * tanhf(th_raw[cell]);
        float sr = fmaxf(expf(sr_raw[cell]), 1e-6f);
        float rr = fminf(fmaxf(2.0f * fmaxf(sx, sy), 1.0f), (float)R_MAX);
        float Rsq = rr * rr;
        s_scal[0] = cosf(th);
        s_scal[1] = sinf(th);
        s_scal[2] = 1.0f / (2.0f * sx * sx + 1e-8f);
        s_scal[3] = 1.0f / (2.0f * sy * sy + 1e-8f);
        s_scal[4] = 1.0f / (2.0f * sr * sr + 1e-8f);
        int n = 0;
        for (int dy = -R_MAX; dy <= R_MAX; dy++) {
            for (int dx = -R_MAX; dx <= R_MAX; dx++) {
                if ((float)(dy * dy + dx * dx) <= Rsq) {
                    int ui = min(max(uc + dy, 0), HL - 1);
                    int vi = min(max(vc + dx, 0), WL - 1);
                    s_dyf[n] = (float)(uc - ui);
                    s_dxf[n] = (float)(vc - vi);
                    s_si[n]  = ui * WL + vi;
                    n++;
                }
            }
        }
        *s_nactp = n;   // <= 49
    }
    __syncthreads();

    const int nact = *s_nactp;
    const int kpad = (nact + 7) & ~7;
    const float ct  = s_scal[0];
    const float st  = s_scal[1];
    const float isx = s_scal[2];
    const float isy = s_scal[3];
    const float isr = s_scal[4];

    if (tid < nact) {
        int si = s_si[tid];
        float fdx = s_dxf[tid];
        float fdy = s_dyf[tid];
        float gl0 = g_guide_lr[si];
        float gl1 = g_guide_lr[HL * WL + si];
        float gl2 = g_guide_lr[2 * HL * WL + si];
        float A = fdx * ct + fdy * st;
        float B = fdy * ct - fdx * st;
        float D = (gl0 * gl0 + gl1 * gl1 + gl2 * gl2) * isr;
        s_p0[tid] = make_float4(A, B, D, 2.0f * gl0 * isr);
        s_p1[tid] = make_float2(2.0f * gl1 * isr, 2.0f * gl2 * isr);
    }
    __syncthreads();

    // ---- phase 1: build W (threads 0-255) / F (threads 256-511) ----
    if (tid < 256) {
        const int p = tid;
        const int ty = p >> 4, tx = p & 15;
        const int y = uc * SCALE + ty;
        const int x = vc * SCALE + tx;
        const float* gpix = guide + y * WH + x;
        const float g0 = gpix[0];
        const float g1 = gpix[HW];
        const float g2 = gpix[2 * HW];
        const float px = ((float)tx - 7.5f) * (1.0f / SCALE);
        const float py = ((float)ty - 7.5f) * (1.0f / SCALE);
        const float pa = px * ct + py * st;
        const float pb = py * ct - px * st;
        const float negE = -(g0 * g0 + g1 * g1 + g2 * g2) * isr;
        const float nisx = -isx, nisy = -isy;

        float den = 0.0f;
        float2* wrow = (float2*)(Wf + p * KSTRIDE_F);
        for (int k = 0; k < kpad; k++) {
            float w = 0.0f;
            if (k < nact) {
                float4 q0 = s_p0[k];
                float2 q1 = s_p1[k];
                float a = pa + q0.x;
                float b = pb + q0.y;
                float t = negE - q0.z;
                t = fmaf(g0, q0.w, t);
                t = fmaf(g1, q1.x, t);
                t = fmaf(g2, q1.y, t);
                t = fmaf(a * a, nisx, t);
                t = fmaf(b * b, nisy, t);
                w = __expf(t);
                den += w;
            }
            uint32_t h = f2tf32(w);
            uint32_t l = f2tf32(w - __uint_as_float(h));
            wrow[k] = make_float2(__uint_as_float(h), __uint_as_float(l));
        }
        s_den[p] = den;
    } else {
        const int t = tid - 256;
        const int c = t & 127;
        float2* frow = (float2*)(Ff + c * KSTRIDE_F);
        for (int k = (t >> 7); k < kpad; k += 2) {
            float f = (k < nact) ? g_feat_t[s_si[k] * C_FEAT + c] : 0.0f;
            uint32_t h = f2tf32(f);
            uint32_t l = f2tf32(f - __uint_as_float(h));
            frow[k] = make_float2(__uint_as_float(h), __uint_as_float(l));
        }
    }
    __syncthreads();

    // ---- phase 2: warp MMAs. warp = (pair, nhalf); 2 mtiles x 8 ntiles ----
    const int pair  = wid >> 1;       // 0..7  -> rows [pair*32, pair*32+32)
    const int nhalf = wid & 1;        // 0/1   -> cols [nhalf*64, +64)
    const int lq = lane >> 2;         // 0..7
    const int lr = lane & 3;          // 0..3

    float acc[2][8][4];
#pragma unroll
    for (int mt = 0; mt < 2; mt++)
#pragma unroll
        for (int nt = 0; nt < 8; nt++)
#pragma unroll
            for (int q = 0; q < 4; q++) acc[mt][nt][q] = 0.0f;

    const float2* W2 = (const float2*)Wf;
    const float2* F2 = (const float2*)Ff;
    const int rowb = pair * 32 + lq;
    const int nb   = nhalf * 64 + lq;
    const int ksteps = kpad >> 3;

    for (int ks = 0; ks < ksteps; ks++) {
        const int kq = ks * 8 + lr;
        uint32_t ah[2][4], al[2][4];
#pragma unroll
        for (int mt = 0; mt < 2; mt++) {
            int r0 = (rowb + mt * 16) * 57;
            float2 A0 = W2[r0 + kq];
            float2 A1 = W2[r0 + 8 * 57 + kq];
            float2 A2 = W2[r0 + kq + 4];
            float2 A3 = W2[r0 + 8 * 57 + kq + 4];
            ah[mt][0] = __float_as_uint(A0.x); al[mt][0] = __float_as_uint(A0.y);
            ah[mt][1] = __float_as_uint(A1.x); al[mt][1] = __float_as_uint(A1.y);
            ah[mt][2] = __float_as_uint(A2.x); al[mt][2] = __float_as_uint(A2.y);
            ah[mt][3] = __float_as_uint(A3.x); al[mt][3] = __float_as_uint(A3.y);
        }
#pragma unroll
        for (int nt = 0; nt < 8; nt++) {
            int nn = (nb + nt * 8) * 57;
            float2 B0 = F2[nn + kq];
            float2 B1 = F2[nn + kq + 4];
            uint32_t b0h = __float_as_uint(B0.x), b0l = __float_as_uint(B0.y);
            uint32_t b1h = __float_as_uint(B1.x), b1l = __float_as_uint(B1.y);
#pragma unroll
            for (int mt = 0; mt < 2; mt++) {
                MMA_TF32(acc[mt][nt], ah[mt][0], ah[mt][1], ah[mt][2], ah[mt][3], b0h, b1h);
                MMA_TF32(acc[mt][nt], al[mt][0], al[mt][1], al[mt][2], al[mt][3], b0h, b1h);
                MMA_TF32(acc[mt][nt], ah[mt][0], ah[mt][1], ah[mt][2], ah[mt][3], b0l, b1l);
            }
        }
    }

    // ---- phase 3: epilogue ----
    float invd[4];
#pragma unroll
    for (int q = 0; q < 4; q++)
        invd[q] = 1.0f / fmaxf(s_den[pair * 32 + q * 8 + lq], 1e-8f);

#pragma unroll
    for (int mt = 0; mt < 2; mt++) {
        const int p0 = pair * 32 + mt * 16 + lq;
        const int y = uc * SCALE + (p0 >> 4);
        const int x = vc * SCALE + (p0 & 15);
        const size_t off = (size_t)y * WH + x;
        const float i0 = invd[mt * 2];
        const float i1 = invd[mt * 2 + 1];
#pragma unroll
        for (int nt = 0; nt < 8; nt++) {
            const int ch = nhalf * 64 + nt * 8 + lr * 2;
            float* o = out + (size_t)ch * HW + off;
            o[0]      = acc[mt][nt][0] * i0;
            o[HW]     = acc[mt][nt][1] * i0;
            o[8]      = acc[mt][nt][2] * i1;
            o[HW + 8] = acc[mt][nt][3] * i1;
        }
    }
}

extern "C" void kernel_launch(void* const* d_in, const int* in_sizes, int n_in,
                              void* d_out, int out_size) {
    const float* feat  = (const float*)d_in[0];
    const float* guide = (const float*)d_in[1];
    const float* sx    = (const float*)d_in[2];
    const float* sy    = (const float*)d_in[3];
    const float* th    = (const float*)d_in[4];
    const float* sr    = (const float*)d_in[5];
    float* out = (float*)d_out;

    cudaFuncSetAttribute(jbu_main_kernel,
                         cudaFuncAttributeMaxDynamicSharedMemorySize, SMEM_BYTES);

    jbu_prep_kernel<<<512, 256>>>(feat, guide);
    dim3 grid(WL, HL);
    jbu_main_kernel<<<grid, 512, SMEM_BYTES>>>(guide, sx, sy, th, sr, out);
}